// round 2
// baseline (speedup 1.0000x reference)
#include <cuda_runtime.h>

// Scratch: per-(n,s) squared distances. N=64, S=16 -> 1024 partials.
__device__ float g_partial[1024];

static constexpr int CHW   = 3 * 128 * 128;   // 49152
static constexpr int CHW4  = CHW / 4;         // 12288 float4s
static constexpr int S     = 16;
static constexpr int NPAIR = 64 * 16;

__global__ __launch_bounds__(512)
void pair_dist_kernel(const float* __restrict__ inputs,
                      const float* __restrict__ samples) {
    const int pair = blockIdx.x;          // 0..1023
    const int n = pair >> 4;
    const int s = pair & 15;

    const float4* __restrict__ in4 =
        reinterpret_cast<const float4*>(inputs + (size_t)n * CHW);
    const float4* __restrict__ sm4 =
        reinterpret_cast<const float4*>(samples + ((size_t)n * S + s) * CHW);

    float acc = 0.0f;
    // 12288 float4 per pair / 512 threads = 24 iterations per thread.
    #pragma unroll 4
    for (int i = threadIdx.x; i < CHW4; i += 512) {
        float4 a = in4[i];
        float4 b = sm4[i];
        float dx = b.x - a.x;
        float dy = b.y - a.y;
        float dz = b.z - a.z;
        float dw = b.w - a.w;
        acc = fmaf(dx, dx, acc);
        acc = fmaf(dy, dy, acc);
        acc = fmaf(dz, dz, acc);
        acc = fmaf(dw, dw, acc);
    }

    // Block reduction: warp shuffle then cross-warp via shared.
    __shared__ float sdata[16];
    #pragma unroll
    for (int o = 16; o > 0; o >>= 1)
        acc += __shfl_down_sync(0xffffffffu, acc, o);

    const int lane = threadIdx.x & 31;
    const int wid  = threadIdx.x >> 5;
    if (lane == 0) sdata[wid] = acc;
    __syncthreads();

    if (wid == 0) {
        acc = (lane < 16) ? sdata[lane] : 0.0f;
        #pragma unroll
        for (int o = 8; o > 0; o >>= 1)
            acc += __shfl_down_sync(0xffffffffu, acc, o);
        if (lane == 0) g_partial[pair] = acc;
    }
}

__global__ void min_sum_kernel(float* __restrict__ out) {
    // 64 threads: thread n takes min over its 16 samples, then sum over n.
    const int n = threadIdx.x;
    float m = g_partial[n * S];
    #pragma unroll
    for (int s = 1; s < S; s++)
        m = fminf(m, g_partial[n * S + s]);

    __shared__ float sh[2];
    #pragma unroll
    for (int o = 16; o > 0; o >>= 1)
        m += __shfl_down_sync(0xffffffffu, m, o);
    if ((threadIdx.x & 31) == 0) sh[threadIdx.x >> 5] = m;
    __syncthreads();
    if (threadIdx.x == 0) out[0] = sh[0] + sh[1];
}

extern "C" void kernel_launch(void* const* d_in, const int* in_sizes, int n_in,
                              void* d_out, int out_size) {
    const float* inputs  = (const float*)d_in[0];   // [64,3,128,128]
    const float* samples = (const float*)d_in[1];   // [64,16,3,128,128]
    float* out = (float*)d_out;

    pair_dist_kernel<<<NPAIR, 512>>>(inputs, samples);
    min_sum_kernel<<<1, 64>>>(out);
}